// round 4
// baseline (speedup 1.0000x reference)
#include <cuda_runtime.h>
#include <math.h>

#define THREADS 256
#define TT      32
#define N_TOK   65536
#define NCTA    (N_TOK / TT)     // 2048
#define DM      128
#define HID     256
#define NN      17
#define NF      32
#define ND      544              // 17*32

// ---- shared memory layout (floats) ----
// ns : node tile [32][544]  (also aliases the staged x tile [32][128] in phase 1)
// buf: phase1/2 h tile [32][256] (8192 f), later 8 per-warp GAT m-buffers (8*612=4896 f)
// adjs: softmaxed adjacency [17][17] (padded to 292)
#define OFF_NS   0
#define SZ_NS    (TT * ND)            // 17408
#define OFF_BUF  (OFF_NS + SZ_NS)     // 17408 (byte off 69632, 16B aligned)
#define SZ_BUF   8192
#define OFF_ADJ  (OFF_BUF + SZ_BUF)   // 25600
#define SZ_ADJ   292
#define SMEM_FLOATS (OFF_ADJ + SZ_ADJ)  // 25892 floats = 103568 B

__device__ __forceinline__ float gelu_f(float v) {
    // exact (erf) GELU, matches jax.nn.gelu(approximate=False)
    return 0.5f * v * (1.0f + erff(v * 0.7071067811865476f));
}

// One GAT layer. Token-local math: each warp owns TT/8 = 4 tokens completely,
// so no CTA-wide barriers are needed inside (only __syncwarp between the
// graph-conv ("mixed") stage and the linear+residual write-back).
// lane == feature f (all ns row accesses stride-1 -> conflict free).
// FINAL=true fuses the coord projection (@Wc + bc) and writes the kernel output.
template<bool FINAL>
__device__ __forceinline__ void gat_layer(
    float* __restrict__ ns, float* __restrict__ buf, float* __restrict__ adjs,
    const float* __restrict__ adjG, const float* __restrict__ WgG,
    const float* __restrict__ bgG,
    const float* __restrict__ Wc, const float* __restrict__ bc,
    float* __restrict__ outp, int tid)
{
    const int lane = tid & 31;
    const int wid  = tid >> 5;

    // row-softmax of adjacency logits -> adjs (17 threads)
    if (tid < NN) {
        float r[NN];
        float mx = -3.0e38f;
        #pragma unroll
        for (int j = 0; j < NN; j++) { r[j] = adjG[tid * NN + j]; mx = fmaxf(mx, r[j]); }
        float s = 0.0f;
        #pragma unroll
        for (int j = 0; j < NN; j++) { r[j] = expf(r[j] - mx); s += r[j]; }
        float inv = 1.0f / s;
        #pragma unroll
        for (int j = 0; j < NN; j++) adjs[tid * NN + j] = r[j] * inv;
    }

    // Wg column for this lane in registers (reused across all 68 node rows)
    float wg[NF];
    #pragma unroll
    for (int g = 0; g < NF; g++) wg[g] = WgG[g * NF + lane];
    const float bgv = bgG[lane];
    float wc0 = 0.0f, wc1 = 0.0f, bc0 = 0.0f, bc1 = 0.0f;
    if (FINAL) { wc0 = Wc[2 * lane]; wc1 = Wc[2 * lane + 1]; bc0 = bc[0]; bc1 = bc[1]; }

    __syncthreads();  // adjs ready; also orders vs previous phase's buf/ns use

    float* wb = buf + wid * (NN * 36);  // per-warp m-staging, padded rows of 36

    for (int tloc = 0; tloc < TT / 8; tloc++) {
        const int t = wid * (TT / 8) + tloc;
        const float* nt = ns + t * ND;

        // mixed[i][lane] = sum_j adj[i][j] * nodes[t][j][lane]
        #pragma unroll 1
        for (int i = 0; i < NN; i++) {
            const float* ar = adjs + i * NN;
            float m = 0.0f;
            #pragma unroll
            for (int j = 0; j < NN; j++) m += ar[j] * nt[j * NF + lane];
            wb[i * 36 + lane] = m;
        }
        __syncwarp();

        // out[i][lane] = gelu(sum_g mixed[i][g] * Wg[g][lane] + bg[lane]) + nodes
        #pragma unroll 1
        for (int i = 0; i < NN; i++) {
            float o = bgv;
            const float4* mp = reinterpret_cast<const float4*>(wb + i * 36);
            #pragma unroll
            for (int q = 0; q < 8; q++) {
                float4 mv = mp[q];  // broadcast (uniform address across warp)
                o += mv.x * wg[4*q] + mv.y * wg[4*q+1] + mv.z * wg[4*q+2] + mv.w * wg[4*q+3];
            }
            const float val = gelu_f(o) + nt[i * NF + lane];
            if (FINAL) {
                // fused coord projection: out[t,i,c] = sum_f val_f * Wc[f,c] + bc[c]
                float s0 = val * wc0;
                float s1 = val * wc1;
                #pragma unroll
                for (int off = 16; off; off >>= 1) {
                    s0 += __shfl_xor_sync(0xffffffffu, s0, off);
                    s1 += __shfl_xor_sync(0xffffffffu, s1, off);
                }
                if (lane == 0) {
                    float2 r2;
                    r2.x = s0 + bc0;
                    r2.y = s1 + bc1;
                    *reinterpret_cast<float2*>(outp + (t * NN + i) * 2) = r2;
                }
            } else {
                ns[t * ND + i * NF + lane] = val;
            }
        }
        __syncwarp();
    }
    __syncthreads();
}

extern "C" __global__ void __launch_bounds__(THREADS, 2)
biogat_kernel(const float* __restrict__ x,
              const float* __restrict__ W1,  const float* __restrict__ b1,
              const float* __restrict__ W2,  const float* __restrict__ b2,
              const float* __restrict__ adj1, const float* __restrict__ Wg1, const float* __restrict__ bg1,
              const float* __restrict__ adj2, const float* __restrict__ Wg2, const float* __restrict__ bg2,
              const float* __restrict__ Wc,  const float* __restrict__ bc,
              float* __restrict__ out)
{
    extern __shared__ float sh[];
    float* ns   = sh + OFF_NS;
    float* buf  = sh + OFF_BUF;
    float* adjs = sh + OFF_ADJ;

    const int tid  = threadIdx.x;
    const int tok0 = blockIdx.x * TT;

    // ---- stage x tile [32][128] into smem (aliases ns; x is dead before ns is written) ----
    {
        const float* xg = x + (size_t)tok0 * DM;
        for (int v = tid; v < TT * DM; v += THREADS) ns[v] = xg[v];
    }
    __syncthreads();

    const int cg = tid & 63;   // 64 column groups of 4
    const int tg = tid >> 6;   // 4 token groups of 8

    // ---- phase 1: h = gelu(x @ W1 + b1) -> buf (hs [32][256]) ----
    float* hs = buf;
    {
        const int col = cg * 4;
        const float4 bv = *reinterpret_cast<const float4*>(b1 + col);
        float a0[8], a1[8], a2[8], a3[8];
        #pragma unroll
        for (int t = 0; t < 8; t++) { a0[t] = bv.x; a1[t] = bv.y; a2[t] = bv.z; a3[t] = bv.w; }
        const float* xr = ns + tg * 8 * DM;
        #pragma unroll 4
        for (int k = 0; k < DM; k++) {
            const float4 w = *reinterpret_cast<const float4*>(W1 + k * HID + col);
            #pragma unroll
            for (int t = 0; t < 8; t++) {
                const float xv = xr[t * DM + k];   // broadcast within warp
                a0[t] += xv * w.x; a1[t] += xv * w.y; a2[t] += xv * w.z; a3[t] += xv * w.w;
            }
        }
        #pragma unroll
        for (int t = 0; t < 8; t++) {
            float4 hv;
            hv.x = gelu_f(a0[t]); hv.y = gelu_f(a1[t]);
            hv.z = gelu_f(a2[t]); hv.w = gelu_f(a3[t]);
            *reinterpret_cast<float4*>(hs + (tg * 8 + t) * HID + col) = hv;
        }
    }
    __syncthreads();

    // ---- phase 2: nodes = h @ W2 + b2 -> ns [32][544] ----
    {
        #pragma unroll
        for (int chunk = 0; chunk < 2; chunk++) {
            const int col = chunk * 256 + cg * 4;
            const float4 bv = *reinterpret_cast<const float4*>(b2 + col);
            float a0[8], a1[8], a2[8], a3[8];
            #pragma unroll
            for (int t = 0; t < 8; t++) { a0[t] = bv.x; a1[t] = bv.y; a2[t] = bv.z; a3[t] = bv.w; }
            const float* hr = hs + tg * 8 * HID;
            #pragma unroll 4
            for (int k = 0; k < HID; k++) {
                const float4 w = *reinterpret_cast<const float4*>(W2 + k * ND + col);
                #pragma unroll
                for (int t = 0; t < 8; t++) {
                    const float hv = hr[t * HID + k];
                    a0[t] += hv * w.x; a1[t] += hv * w.y; a2[t] += hv * w.z; a3[t] += hv * w.w;
                }
            }
            #pragma unroll
            for (int t = 0; t < 8; t++) {
                float4 r;
                r.x = a0[t]; r.y = a1[t]; r.z = a2[t]; r.w = a3[t];
                *reinterpret_cast<float4*>(ns + (tg * 8 + t) * ND + col) = r;
            }
        }
        // tail columns 512..543: remap so ALL 256 threads stay busy
        {
            const int cg2 = tid & 7;     // 8 col groups of 4
            const int tk  = tid >> 3;    // 32 tokens, 1 per thread
            const int col = 512 + cg2 * 4;
            const float4 bv = *reinterpret_cast<const float4*>(b2 + col);
            float c0 = bv.x, c1 = bv.y, c2 = bv.z, c3 = bv.w;
            const float* hr = hs + tk * HID;
            #pragma unroll 4
            for (int k = 0; k < HID; k++) {
                const float4 w = *reinterpret_cast<const float4*>(W2 + k * ND + col);
                const float hv = hr[k];
                c0 += hv * w.x; c1 += hv * w.y; c2 += hv * w.z; c3 += hv * w.w;
            }
            float4 r; r.x = c0; r.y = c1; r.z = c2; r.w = c3;
            *reinterpret_cast<float4*>(ns + tk * ND + col) = r;
        }
    }
    __syncthreads();

    // ---- GAT1, then GAT2 fused with coord projection ----
    gat_layer<false>(ns, buf, adjs, adj1, Wg1, bg1, Wc, bc, nullptr, tid);
    gat_layer<true >(ns, buf, adjs, adj2, Wg2, bg2, Wc, bc,
                     out + (size_t)tok0 * NN * 2, tid);
}

extern "C" void kernel_launch(void* const* d_in, const int* in_sizes, int n_in,
                              void* d_out, int out_size) {
    const float* x    = (const float*)d_in[0];
    const float* W1   = (const float*)d_in[1];
    const float* b1   = (const float*)d_in[2];
    const float* W2   = (const float*)d_in[3];
    const float* b2   = (const float*)d_in[4];
    const float* adj1 = (const float*)d_in[5];
    const float* Wg1  = (const float*)d_in[6];
    const float* bg1  = (const float*)d_in[7];
    const float* adj2 = (const float*)d_in[8];
    const float* Wg2  = (const float*)d_in[9];
    const float* bg2  = (const float*)d_in[10];
    const float* Wc   = (const float*)d_in[11];
    const float* bc   = (const float*)d_in[12];
    float* out = (float*)d_out;

    const size_t smem = SMEM_FLOATS * sizeof(float);
    cudaFuncSetAttribute((const void*)biogat_kernel,
                         cudaFuncAttributeMaxDynamicSharedMemorySize, (int)smem);
    biogat_kernel<<<NCTA, THREADS, smem>>>(x, W1, b1, W2, b2,
                                           adj1, Wg1, bg1,
                                           adj2, Wg2, bg2,
                                           Wc, bc, out);
}